// round 12
// baseline (speedup 1.0000x reference)
#include <cuda_runtime.h>

#define NB   8
#define NC   64
#define MH   256
#define MW   256
#define NPIX (MH*MW)
#define CAP  8192
#define TOPK 4096

// -------- device scratch (no allocations allowed) --------
__device__ float g_desc_t[NB * NPIX * NC];        // normalized desc, NHWC
__device__ int   g_count[NB];
__device__ int   g_minbits;
__device__ int   g_maxbits;
__device__ int   g_kp_pix[NB * CAP];
__device__ float g_kp_var[NB * CAP];
__device__ float g_kp_rel[NB * CAP];
__device__ unsigned long long g_keys[NB * CAP];
__device__ int   g_sel[NB * TOPK];

// -------- helpers --------
__device__ __forceinline__ unsigned f2s(float f) {
    unsigned u = __float_as_uint(f);
    return (u & 0x80000000u) ? ~u : (u ^ 0x80000000u);
}
__device__ __forceinline__ float s2f(unsigned s) {
    unsigned u = (s & 0x80000000u) ? (s ^ 0x80000000u) : ~s;
    return __uint_as_float(u);
}
__device__ __forceinline__ void cubicw(float t, float* w) {
    const float A = -0.75f;
    float t1 = t + 1.0f;
    w[0] = ((A * t1 - 5.0f * A) * t1 + 8.0f * A) * t1 - 4.0f * A;
    w[1] = ((A + 2.0f) * t - (A + 3.0f)) * t * t + 1.0f;
    float u = 1.0f - t;
    w[2] = ((A + 2.0f) * u - (A + 3.0f)) * u * u + 1.0f;
    float t2 = 2.0f - t;
    w[3] = ((A * t2 - 5.0f * A) * t2 + 8.0f * A) * t2 - 4.0f * A;
}
// Unnorm: HLO reciprocal rewrite (p/1023 -> p*fl(1/1023)), *256 folded (exact), -0.5.
__device__ __forceinline__ float unnorm(float p) {
    const float C = 256.0f / 1023.0f;   // = 256 * fl(1/1023) exactly
    return __fsub_rn(__fmul_rn(p, C), 0.5f);
}

// -------- kernels --------
__global__ void k_init() {
    int t = threadIdx.x;
    if (t < NB) g_count[t] = 0;
    if (t == 0) { g_minbits = 0x7F800000; g_maxbits = 0; }
}

// desc [B,C,H,W] -> g_desc_t [B,H*W,C], fused per-pixel L2 inv-norm
__global__ void k_transpose(const float* __restrict__ desc) {
    __shared__ float sh[NC][33];
    __shared__ float sinv[32];
    int b    = blockIdx.x >> 11;           // 2048 tiles per batch
    int base = (blockIdx.x & 2047) * 32;   // 32 pixels per tile
    int tx = threadIdx.x, ty = threadIdx.y;
#pragma unroll
    for (int i = 0; i < 8; i++) {
        int c = i * 8 + ty;
        sh[c][tx] = desc[(b * NC + c) * NPIX + base + tx];
    }
    __syncthreads();
    int lin = ty * 32 + tx;
    if (lin < 32) {
        float ss = 0.f;
#pragma unroll
        for (int c = 0; c < NC; c++) { float v = sh[c][lin]; ss += v * v; }
        sinv[lin] = 1.0f / fmaxf(sqrtf(ss), 1e-12f);
    }
    __syncthreads();
#pragma unroll
    for (int kk = 0; kk < 8; kk++) {
        int idx = kk * 256 + lin;
        int p = idx >> 6, c = idx & 63;
        g_desc_t[((b * NPIX + base + p) << 6) + c] = sh[c][p] * sinv[p];
    }
}

// NMS + bilinear variance sample + global min/max + compaction
__global__ void k_nms(const float* __restrict__ rel, const float* __restrict__ var) {
    int t = blockIdx.x * blockDim.x + threadIdx.x;
    int b = t >> 16, pix = t & (NPIX - 1);
    int y = pix >> 8, x = pix & 255;
    const float* rb = rel + b * NPIX;
    float v = __ldg(rb + pix);
    int ylo = y - 2 < 0 ? 0 : y - 2, yhi = y + 2 > MH - 1 ? MH - 1 : y + 2;
    int xlo = x - 2 < 0 ? 0 : x - 2, xhi = x + 2 > MW - 1 ? MW - 1 : x + 2;
    float lm = -3.0e38f;
    for (int yy = ylo; yy <= yhi; yy++) {
        const float* rr = rb + (yy << 8);
        for (int xx = xlo; xx <= xhi; xx++) lm = fmaxf(lm, __ldg(rr + xx));
    }
    bool kp = (v == lm) && (v > 0.05f);
    if (kp || pix == 0) {   // pix==0 also covers padding rows' var_s contribution
        const float* vb = var + b * NPIX;
        float ixf = unnorm((float)(4 * x));
        float iyf = unnorm((float)(4 * y));
        float fx = floorf(ixf), fy = floorf(iyf);
        int x0 = (int)fx, y0 = (int)fy;
        float tx = __fsub_rn(ixf, fx), ty = __fsub_rn(iyf, fy);
        float omtx = __fsub_rn(1.0f, tx), omty = __fsub_rn(1.0f, ty);
        auto ld = [&](int yy, int xx) -> float {
            return ((unsigned)yy < MH && (unsigned)xx < MW) ? __ldg(vb + (yy << 8) + xx) : 0.f;
        };
        float v00 = ld(y0, x0),     v01 = ld(y0, x0 + 1);
        float v10 = ld(y0 + 1, x0), v11 = ld(y0 + 1, x0 + 1);
        // Bilinear variant A: literal reference op sequence, every op IEEE-rounded.
        float top = __fadd_rn(__fmul_rn(v00, omtx), __fmul_rn(v01, tx));
        float bot = __fadd_rn(__fmul_rn(v10, omtx), __fmul_rn(v11, tx));
        float vs  = __fadd_rn(__fmul_rn(top, omty), __fmul_rn(bot, ty));
        atomicMin(&g_minbits, __float_as_int(vs));   // vs >= 0 -> int bits monotone
        atomicMax(&g_maxbits, __float_as_int(vs));
        if (kp) {
            int idx = atomicAdd(&g_count[b], 1);
            if (idx < CAP) {
                g_kp_pix[b * CAP + idx] = pix;
                g_kp_var[b * CAP + idx] = vs;
                g_kp_rel[b * CAP + idx] = v;
            }
        }
    }
}

// score + 64-bit sort key (descending score, pixel-ascending tie-break)
__global__ void k_keys() {
    int t = blockIdx.x * blockDim.x + threadIdx.x;
    int b = t / CAP, i = t % CAP;
    int cnt = g_count[b]; if (cnt > CAP) cnt = CAP;
    unsigned long long key = ~0ull;
    if (i < cnt) {
        int pixel = g_kp_pix[b * CAP + i];
        float sc;
        if (pixel == 0) {
            sc = -1.0f;
        } else {
            float mn = __int_as_float(g_minbits);
            float mx = __int_as_float(g_maxbits);
            float vs = g_kp_var[b * CAP + i];
            float denom = __fadd_rn(__fsub_rn(mx, mn), 1e-6f);
            // HLO scalar-division hoist: divide(X, broadcast(s)) -> X * broadcast(1/s)
            float r  = __fdiv_rn(1.0f, denom);
            float tt = __fsub_rn(vs, mn);
            float vn = __fmul_rn(tt, r);
            // Backend precise: unfused subtract and multiply
            float score_var = __fsub_rn(1.0f, vn);
            sc = __fmul_rn(g_kp_rel[b * CAP + i], score_var);
        }
        key = ((unsigned long long)(~f2s(sc)) << 32) | (unsigned)pixel;
    }
    g_keys[t] = key;
}

// one block per batch, bitonic sort of CAP u64 keys in shared memory
__global__ void k_sort() {
    extern __shared__ unsigned long long sk[];
    int b = blockIdx.x;
    for (int i = threadIdx.x; i < CAP; i += blockDim.x) sk[i] = g_keys[b * CAP + i];
    __syncthreads();
    for (int k = 2; k <= CAP; k <<= 1) {
        for (int j = k >> 1; j > 0; j >>= 1) {
            for (int i = threadIdx.x; i < CAP; i += blockDim.x) {
                int ixj = i ^ j;
                if (ixj > i) {
                    bool asc = ((i & k) == 0);
                    unsigned long long a = sk[i], c = sk[ixj];
                    if ((a > c) == asc) { sk[i] = c; sk[ixj] = a; }
                }
            }
            __syncthreads();
        }
    }
    for (int i = threadIdx.x; i < CAP; i += blockDim.x) g_keys[b * CAP + i] = sk[i];
}

// emit mk_top / sc_top, record selected pixel per slot
__global__ void k_emit(float* __restrict__ out_mk, float* __restrict__ out_sc) {
    int t = blockIdx.x * blockDim.x + threadIdx.x;
    int b = t / TOPK, k = t % TOPK;
    unsigned long long key = g_keys[b * CAP + k];
    int pixel; float sc;
    if (key == ~0ull) { pixel = 0; sc = -1.0f; }
    else {
        pixel = (int)(unsigned)(key & 0xFFFFFFFFull);
        sc = s2f(~(unsigned)(key >> 32));
    }
    int x = pixel & 255, y = pixel >> 8;
    out_mk[t * 2 + 0] = (float)(4 * x);
    out_mk[t * 2 + 1] = (float)(4 * y);
    out_sc[t] = sc;
    g_sel[t] = pixel;
}

// bicubic sample of normalized desc + final L2 normalize; one warp per point
__global__ void k_feats(float* __restrict__ out_ft) {
    int w    = (blockIdx.x * blockDim.x + threadIdx.x) >> 5;
    int lane = threadIdx.x & 31;
    int b = w / TOPK;
    int pixel = g_sel[w];
    int x = pixel & 255, y = pixel >> 8;
    float ixf = unnorm((float)(4 * x));
    float iyf = unnorm((float)(4 * y));
    float fx = floorf(ixf), fy = floorf(iyf);
    int x0 = (int)fx, y0 = (int)fy;
    float tx = ixf - fx, ty = iyf - fy;
    float wx[4], wy[4];
    cubicw(tx, wx);
    cubicw(ty, wy);
    float a0 = 0.f, a1 = 0.f;
#pragma unroll
    for (int j = 0; j < 4; j++) {
        int yy = y0 - 1 + j;
        if ((unsigned)yy >= MH) continue;
#pragma unroll
        for (int i = 0; i < 4; i++) {
            int xx = x0 - 1 + i;
            if ((unsigned)xx >= MW) continue;
            float wgt = wy[j] * wx[i];
            const float* p = g_desc_t + (((b * NPIX) + (yy << 8) + xx) << 6);
            a0 += wgt * __ldg(p + lane);
            a1 += wgt * __ldg(p + lane + 32);
        }
    }
    float ss = a0 * a0 + a1 * a1;
#pragma unroll
    for (int off = 16; off > 0; off >>= 1) ss += __shfl_xor_sync(0xFFFFFFFFu, ss, off);
    float inv = 1.0f / fmaxf(sqrtf(ss), 1e-12f);
    out_ft[w * 64 + lane]      = a0 * inv;
    out_ft[w * 64 + lane + 32] = a1 * inv;
}

// -------- launch --------
extern "C" void kernel_launch(void* const* d_in, const int* in_sizes, int n_in,
                              void* d_out, int out_size) {
    const float* rel  = (const float*)d_in[0];
    const float* var  = (const float*)d_in[1];
    const float* desc = (const float*)d_in[2];
    float* out    = (float*)d_out;
    float* out_mk = out;                        // [8,4096,2]
    float* out_sc = out + NB * TOPK * 2;        // [8,4096]
    float* out_ft = out + NB * TOPK * 3;        // [8,4096,64]

    static_assert(CAP * sizeof(unsigned long long) == 65536, "smem size");
    cudaFuncSetAttribute(k_sort, cudaFuncAttributeMaxDynamicSharedMemorySize, 65536);

    k_init<<<1, 32>>>();
    k_transpose<<<NB * (NPIX / 32), dim3(32, 8)>>>(desc);
    k_nms<<<(NB * NPIX) / 256, 256>>>(rel, var);
    k_keys<<<(NB * CAP) / 256, 256>>>();
    k_sort<<<NB, 1024, 65536>>>();
    k_emit<<<(NB * TOPK) / 256, 256>>>(out_mk, out_sc);
    k_feats<<<(NB * TOPK) / 8, 256>>>(out_ft);
}

// round 13
// speedup vs baseline: 1.3339x; 1.3339x over previous
#include <cuda_runtime.h>

#define NB   8
#define NC   64
#define MH   256
#define MW   256
#define NPIX (MH*MW)
#define CAP  4096
#define TOPK 4096

// -------- device scratch (no allocations allowed) --------
__device__ float g_desc_t[NB * NPIX * NC];        // normalized desc, NHWC
__device__ int   g_count[NB];
__device__ int   g_minbits;
__device__ int   g_maxbits;
__device__ int   g_kp_pix[NB * CAP];
__device__ float g_kp_var[NB * CAP];
__device__ float g_kp_rel[NB * CAP];
__device__ unsigned long long g_keys[NB * CAP];

// -------- helpers --------
__device__ __forceinline__ unsigned f2s(float f) {
    unsigned u = __float_as_uint(f);
    return (u & 0x80000000u) ? ~u : (u ^ 0x80000000u);
}
__device__ __forceinline__ float s2f(unsigned s) {
    unsigned u = (s & 0x80000000u) ? (s ^ 0x80000000u) : ~s;
    return __uint_as_float(u);
}
__device__ __forceinline__ void cubicw(float t, float* w) {
    const float A = -0.75f;
    float t1 = t + 1.0f;
    w[0] = ((A * t1 - 5.0f * A) * t1 + 8.0f * A) * t1 - 4.0f * A;
    w[1] = ((A + 2.0f) * t - (A + 3.0f)) * t * t + 1.0f;
    float u = 1.0f - t;
    w[2] = ((A + 2.0f) * u - (A + 3.0f)) * u * u + 1.0f;
    float t2 = 2.0f - t;
    w[3] = ((A * t2 - 5.0f * A) * t2 + 8.0f * A) * t2 - 4.0f * A;
}
// Unnorm: HLO reciprocal rewrite (p/1023 -> p*fl(1/1023)), *256 folded (exact), -0.5.
__device__ __forceinline__ float unnorm(float p) {
    const float C = 256.0f / 1023.0f;   // = 256 * fl(1/1023) exactly
    return __fsub_rn(__fmul_rn(p, C), 0.5f);
}

// -------- kernels --------
__global__ void k_init() {
    int t = threadIdx.x;
    if (t < NB) g_count[t] = 0;
    if (t == 0) { g_minbits = 0x7F800000; g_maxbits = 0; }
}

// desc [B,C,H,W] -> g_desc_t [B,H*W,C], fused per-pixel L2 inv-norm.
// 64px x 64ch tiles, float4 global loads AND stores.
__global__ void k_transpose(const float* __restrict__ desc) {
    __shared__ float sh[NC][65];
    __shared__ float sinv[64];
    int b    = blockIdx.x >> 10;           // 1024 tiles per batch
    int base = (blockIdx.x & 1023) * 64;   // 64 pixels per tile
    int tid  = threadIdx.x;                // 256 threads

    // load 64ch x 16 float4 (1024 float4), coalesced along pixels
#pragma unroll
    for (int k = 0; k < 4; k++) {
        int fidx = tid + k * 256;
        int c = fidx >> 4, q = fidx & 15;
        float4 v = *(const float4*)(desc + ((b * NC + c) << 16) + base + q * 4);
        sh[c][q * 4 + 0] = v.x; sh[c][q * 4 + 1] = v.y;
        sh[c][q * 4 + 2] = v.z; sh[c][q * 4 + 3] = v.w;
    }
    __syncthreads();
    // per-pixel sum of squares: 4 threads per pixel x 16 channels each
    {
        int px = tid >> 2, part = tid & 3;
        float ss = 0.f;
#pragma unroll
        for (int i = 0; i < 16; i++) { float v = sh[part * 16 + i][px]; ss += v * v; }
        ss += __shfl_xor_sync(0xFFFFFFFFu, ss, 1);
        ss += __shfl_xor_sync(0xFFFFFFFFu, ss, 2);
        if (part == 0) sinv[px] = 1.0f / fmaxf(sqrtf(ss), 1e-12f);
    }
    __syncthreads();
    // store: 64px x 16 float4, contiguous per pixel
#pragma unroll
    for (int k = 0; k < 4; k++) {
        int fidx = tid + k * 256;
        int px = fidx >> 4, q = fidx & 15;
        float s = sinv[px];
        float4 v;
        v.x = sh[q * 4 + 0][px] * s; v.y = sh[q * 4 + 1][px] * s;
        v.z = sh[q * 4 + 2][px] * s; v.w = sh[q * 4 + 3][px] * s;
        *(float4*)(g_desc_t + (((b << 16) + base + px) << 6) + q * 4) = v;
    }
}

// NMS + bilinear variance sample + global min/max + compaction
__global__ void k_nms(const float* __restrict__ rel, const float* __restrict__ var) {
    int t = blockIdx.x * blockDim.x + threadIdx.x;
    int b = t >> 16, pix = t & (NPIX - 1);
    int y = pix >> 8, x = pix & 255;
    const float* rb = rel + b * NPIX;
    float v = __ldg(rb + pix);
    int ylo = y - 2 < 0 ? 0 : y - 2, yhi = y + 2 > MH - 1 ? MH - 1 : y + 2;
    int xlo = x - 2 < 0 ? 0 : x - 2, xhi = x + 2 > MW - 1 ? MW - 1 : x + 2;
    float lm = -3.0e38f;
    for (int yy = ylo; yy <= yhi; yy++) {
        const float* rr = rb + (yy << 8);
        for (int xx = xlo; xx <= xhi; xx++) lm = fmaxf(lm, __ldg(rr + xx));
    }
    bool kp = (v == lm) && (v > 0.05f);
    if (kp || pix == 0) {   // pix==0 also covers padding rows' var_s contribution
        const float* vb = var + b * NPIX;
        float ixf = unnorm((float)(4 * x));
        float iyf = unnorm((float)(4 * y));
        float fx = floorf(ixf), fy = floorf(iyf);
        int x0 = (int)fx, y0 = (int)fy;
        float tx = __fsub_rn(ixf, fx), ty = __fsub_rn(iyf, fy);
        float omtx = __fsub_rn(1.0f, tx), omty = __fsub_rn(1.0f, ty);
        auto ld = [&](int yy, int xx) -> float {
            return ((unsigned)yy < MH && (unsigned)xx < MW) ? __ldg(vb + (yy << 8) + xx) : 0.f;
        };
        float v00 = ld(y0, x0),     v01 = ld(y0, x0 + 1);
        float v10 = ld(y0 + 1, x0), v11 = ld(y0 + 1, x0 + 1);
        // fully unfused bilinear (matches reference bit-exactly)
        float top = __fadd_rn(__fmul_rn(v00, omtx), __fmul_rn(v01, tx));
        float bot = __fadd_rn(__fmul_rn(v10, omtx), __fmul_rn(v11, tx));
        float vs  = __fadd_rn(__fmul_rn(top, omty), __fmul_rn(bot, ty));
        atomicMin(&g_minbits, __float_as_int(vs));   // vs >= 0 -> int bits monotone
        atomicMax(&g_maxbits, __float_as_int(vs));
        if (kp) {
            int idx = atomicAdd(&g_count[b], 1);
            if (idx < CAP) {
                g_kp_pix[b * CAP + idx] = pix;
                g_kp_var[b * CAP + idx] = vs;
                g_kp_rel[b * CAP + idx] = v;
            }
        }
    }
}

// fused: score/key computation + bitonic sort (one block per batch)
__global__ void k_sort() {
    __shared__ unsigned long long sk[CAP];
    int b = blockIdx.x;
    int cnt = g_count[b]; if (cnt > CAP) cnt = CAP;
    float mn = __int_as_float(g_minbits);
    float mx = __int_as_float(g_maxbits);
    float denom = __fadd_rn(__fsub_rn(mx, mn), 1e-6f);
    // HLO scalar-division hoist: divide(X, broadcast(s)) -> X * broadcast(1/s)
    float r = __fdiv_rn(1.0f, denom);
    for (int i = threadIdx.x; i < CAP; i += blockDim.x) {
        unsigned long long key = ~0ull;
        if (i < cnt) {
            int pixel = g_kp_pix[b * CAP + i];
            float sc;
            if (pixel == 0) {
                sc = -1.0f;
            } else {
                float tt = __fsub_rn(g_kp_var[b * CAP + i], mn);
                float vn = __fmul_rn(tt, r);
                float score_var = __fsub_rn(1.0f, vn);
                sc = __fmul_rn(g_kp_rel[b * CAP + i], score_var);
            }
            key = ((unsigned long long)(~f2s(sc)) << 32) | (unsigned)pixel;
        }
        sk[i] = key;
    }
    __syncthreads();
    for (int k = 2; k <= CAP; k <<= 1) {
        for (int j = k >> 1; j > 0; j >>= 1) {
            for (int i = threadIdx.x; i < CAP; i += blockDim.x) {
                int ixj = i ^ j;
                if (ixj > i) {
                    bool asc = ((i & k) == 0);
                    unsigned long long a = sk[i], c = sk[ixj];
                    if ((a > c) == asc) { sk[i] = c; sk[ixj] = a; }
                }
            }
            __syncthreads();
        }
    }
    for (int i = threadIdx.x; i < CAP; i += blockDim.x) g_keys[b * CAP + i] = sk[i];
}

// fused: emit mk/sc + bicubic sample + final L2 normalize; one warp per point
__global__ void k_feats(float* __restrict__ out_mk, float* __restrict__ out_sc,
                        float* __restrict__ out_ft) {
    int w    = (blockIdx.x * blockDim.x + threadIdx.x) >> 5;
    int lane = threadIdx.x & 31;
    int b = w >> 12;                       // TOPK = 4096 points per batch
    unsigned long long key = g_keys[w];    // CAP == TOPK: dense
    int pixel; float sc;
    if (key == ~0ull) { pixel = 0; sc = -1.0f; }
    else {
        pixel = (int)(unsigned)(key & 0xFFFFFFFFull);
        sc = s2f(~(unsigned)(key >> 32));
    }
    int x = pixel & 255, y = pixel >> 8;
    if (lane == 0) {
        out_mk[w * 2 + 0] = (float)(4 * x);
        out_mk[w * 2 + 1] = (float)(4 * y);
        out_sc[w] = sc;
    }
    float ixf = unnorm((float)(4 * x));
    float iyf = unnorm((float)(4 * y));
    float fx = floorf(ixf), fy = floorf(iyf);
    int x0 = (int)fx, y0 = (int)fy;
    float tx = ixf - fx, ty = iyf - fy;
    float wx[4], wy[4];
    cubicw(tx, wx);
    cubicw(ty, wy);
    float a0 = 0.f, a1 = 0.f;
#pragma unroll
    for (int j = 0; j < 4; j++) {
        int yy = y0 - 1 + j;
        if ((unsigned)yy >= MH) continue;
#pragma unroll
        for (int i = 0; i < 4; i++) {
            int xx = x0 - 1 + i;
            if ((unsigned)xx >= MW) continue;
            float wgt = wy[j] * wx[i];
            const float2* p = (const float2*)(g_desc_t) + ((b << 16) + (yy << 8) + xx) * 32 + lane;
            float2 v = __ldg(p);
            a0 += wgt * v.x;
            a1 += wgt * v.y;
        }
    }
    float ss = a0 * a0 + a1 * a1;
#pragma unroll
    for (int off = 16; off > 0; off >>= 1) ss += __shfl_xor_sync(0xFFFFFFFFu, ss, off);
    float inv = 1.0f / fmaxf(sqrtf(ss), 1e-12f);
    float2 o; o.x = a0 * inv; o.y = a1 * inv;
    ((float2*)out_ft)[w * 32 + lane] = o;
}

// -------- launch --------
extern "C" void kernel_launch(void* const* d_in, const int* in_sizes, int n_in,
                              void* d_out, int out_size) {
    const float* rel  = (const float*)d_in[0];
    const float* var  = (const float*)d_in[1];
    const float* desc = (const float*)d_in[2];
    float* out    = (float*)d_out;
    float* out_mk = out;                        // [8,4096,2]
    float* out_sc = out + NB * TOPK * 2;        // [8,4096]
    float* out_ft = out + NB * TOPK * 3;        // [8,4096,64]

    k_init<<<1, 32>>>();
    k_transpose<<<NB * (NPIX / 64), 256>>>(desc);
    k_nms<<<(NB * NPIX) / 256, 256>>>(rel, var);
    k_sort<<<NB, 1024>>>();
    k_feats<<<(NB * TOPK) / 8, 256>>>(out_mk, out_sc, out_ft);
}

// round 16
// speedup vs baseline: 1.3988x; 1.0486x over previous
#include <cuda_runtime.h>

#define NB   8
#define NC   64
#define MH   256
#define MW   256
#define NPIX (MH*MW)
#define CAP  4096
#define TOPK 4096

// -------- device scratch (no allocations allowed) --------
__device__ float g_desc_t[NB * NPIX * NC];        // normalized desc, NHWC
__device__ int   g_count[NB];
__device__ int   g_minbits;
__device__ int   g_maxbits;
__device__ int   g_kp_pix[NB * CAP];
__device__ float g_kp_var[NB * CAP];
__device__ float g_kp_rel[NB * CAP];
__device__ unsigned long long g_keys[NB * CAP];

// -------- helpers --------
__device__ __forceinline__ unsigned f2s(float f) {
    unsigned u = __float_as_uint(f);
    return (u & 0x80000000u) ? ~u : (u ^ 0x80000000u);
}
__device__ __forceinline__ float s2f(unsigned s) {
    unsigned u = (s & 0x80000000u) ? (s ^ 0x80000000u) : ~s;
    return __uint_as_float(u);
}
__device__ __forceinline__ void cubicw(float t, float* w) {
    const float A = -0.75f;
    float t1 = t + 1.0f;
    w[0] = ((A * t1 - 5.0f * A) * t1 + 8.0f * A) * t1 - 4.0f * A;
    w[1] = ((A + 2.0f) * t - (A + 3.0f)) * t * t + 1.0f;
    float u = 1.0f - t;
    w[2] = ((A + 2.0f) * u - (A + 3.0f)) * u * u + 1.0f;
    float t2 = 2.0f - t;
    w[3] = ((A * t2 - 5.0f * A) * t2 + 8.0f * A) * t2 - 4.0f * A;
}
// Unnorm: HLO reciprocal rewrite (p/1023 -> p*fl(1/1023)), *256 folded (exact), -0.5.
__device__ __forceinline__ float unnorm(float p) {
    const float C = 256.0f / 1023.0f;   // = 256 * fl(1/1023) exactly
    return __fsub_rn(__fmul_rn(p, C), 0.5f);
}

// -------- kernels --------
__global__ void k_init() {
    int t = threadIdx.x;
    if (t < NB) g_count[t] = 0;
    if (t == 0) { g_minbits = 0x7F800000; g_maxbits = 0; }
}

// desc [B,C,H,W] -> g_desc_t [B,H*W,C], fused per-pixel L2 inv-norm.
// 64px x 64ch tiles, float4 global loads AND stores.
__global__ void k_transpose(const float* __restrict__ desc) {
    __shared__ float sh[NC][65];
    __shared__ float sinv[64];
    int b    = blockIdx.x >> 10;           // 1024 tiles per batch
    int base = (blockIdx.x & 1023) * 64;   // 64 pixels per tile
    int tid  = threadIdx.x;                // 256 threads

    // load 64ch x 16 float4 (1024 float4), coalesced along pixels
#pragma unroll
    for (int k = 0; k < 4; k++) {
        int fidx = tid + k * 256;
        int c = fidx >> 4, q = fidx & 15;
        float4 v = *(const float4*)(desc + ((b * NC + c) << 16) + base + q * 4);
        sh[c][q * 4 + 0] = v.x; sh[c][q * 4 + 1] = v.y;
        sh[c][q * 4 + 2] = v.z; sh[c][q * 4 + 3] = v.w;
    }
    __syncthreads();
    // per-pixel sum of squares: 4 threads per pixel x 16 channels each
    {
        int px = tid >> 2, part = tid & 3;
        float ss = 0.f;
#pragma unroll
        for (int i = 0; i < 16; i++) { float v = sh[part * 16 + i][px]; ss += v * v; }
        ss += __shfl_xor_sync(0xFFFFFFFFu, ss, 1);
        ss += __shfl_xor_sync(0xFFFFFFFFu, ss, 2);
        if (part == 0) sinv[px] = 1.0f / fmaxf(sqrtf(ss), 1e-12f);
    }
    __syncthreads();
    // store: 64px x 16 float4, contiguous per pixel
#pragma unroll
    for (int k = 0; k < 4; k++) {
        int fidx = tid + k * 256;
        int px = fidx >> 4, q = fidx & 15;
        float s = sinv[px];
        float4 v;
        v.x = sh[q * 4 + 0][px] * s; v.y = sh[q * 4 + 1][px] * s;
        v.z = sh[q * 4 + 2][px] * s; v.w = sh[q * 4 + 3][px] * s;
        *(float4*)(g_desc_t + (((b << 16) + base + px) << 6) + q * 4) = v;
    }
}

// NMS + bilinear variance sample + global min/max + compaction
__global__ void k_nms(const float* __restrict__ rel, const float* __restrict__ var) {
    int t = blockIdx.x * blockDim.x + threadIdx.x;
    int b = t >> 16, pix = t & (NPIX - 1);
    int y = pix >> 8, x = pix & 255;
    const float* rb = rel + b * NPIX;
    float v = __ldg(rb + pix);
    int ylo = y - 2 < 0 ? 0 : y - 2, yhi = y + 2 > MH - 1 ? MH - 1 : y + 2;
    int xlo = x - 2 < 0 ? 0 : x - 2, xhi = x + 2 > MW - 1 ? MW - 1 : x + 2;
    float lm = -3.0e38f;
    for (int yy = ylo; yy <= yhi; yy++) {
        const float* rr = rb + (yy << 8);
        for (int xx = xlo; xx <= xhi; xx++) lm = fmaxf(lm, __ldg(rr + xx));
    }
    bool kp = (v == lm) && (v > 0.05f);
    if (kp || pix == 0) {   // pix==0 also covers padding rows' var_s contribution
        const float* vb = var + b * NPIX;
        float ixf = unnorm((float)(4 * x));
        float iyf = unnorm((float)(4 * y));
        float fx = floorf(ixf), fy = floorf(iyf);
        int x0 = (int)fx, y0 = (int)fy;
        float tx = __fsub_rn(ixf, fx), ty = __fsub_rn(iyf, fy);
        float omtx = __fsub_rn(1.0f, tx), omty = __fsub_rn(1.0f, ty);
        auto ld = [&](int yy, int xx) -> float {
            return ((unsigned)yy < MH && (unsigned)xx < MW) ? __ldg(vb + (yy << 8) + xx) : 0.f;
        };
        float v00 = ld(y0, x0),     v01 = ld(y0, x0 + 1);
        float v10 = ld(y0 + 1, x0), v11 = ld(y0 + 1, x0 + 1);
        // fully unfused bilinear (matches reference bit-exactly)
        float top = __fadd_rn(__fmul_rn(v00, omtx), __fmul_rn(v01, tx));
        float bot = __fadd_rn(__fmul_rn(v10, omtx), __fmul_rn(v11, tx));
        float vs  = __fadd_rn(__fmul_rn(top, omty), __fmul_rn(bot, ty));
        atomicMin(&g_minbits, __float_as_int(vs));   // vs >= 0 -> int bits monotone
        atomicMax(&g_maxbits, __float_as_int(vs));
        if (kp) {
            int idx = atomicAdd(&g_count[b], 1);
            if (idx < CAP) {
                g_kp_pix[b * CAP + idx] = pix;
                g_kp_var[b * CAP + idx] = vs;
                g_kp_rel[b * CAP + idx] = v;
            }
        }
    }
}

// fused: score/key computation + register/shuffle bitonic sort (one block per batch)
// Thread t owns elements i = 4t+r. j=1,2 in-register; j=4..64 via 64-bit shfl_xor
// (partner lane = lane ^ (j/4) <= 16, same warp); j>=128 via smem+barrier.
__global__ void k_sort() {
    __shared__ unsigned long long sk[CAP];
    int b = blockIdx.x;
    int t = threadIdx.x;                   // 1024 threads
    int cnt = g_count[b]; if (cnt > CAP) cnt = CAP;
    float mn = __int_as_float(g_minbits);
    float mx = __int_as_float(g_maxbits);
    float denom = __fadd_rn(__fsub_rn(mx, mn), 1e-6f);
    // HLO scalar-division hoist: divide(X, broadcast(s)) -> X * broadcast(1/s)
    float r = __fdiv_rn(1.0f, denom);

    unsigned long long v[4];
#pragma unroll
    for (int rr = 0; rr < 4; rr++) {
        int i = 4 * t + rr;
        unsigned long long key = ~0ull;
        if (i < cnt) {
            int pixel = g_kp_pix[b * CAP + i];
            float sc;
            if (pixel == 0) {
                sc = -1.0f;
            } else {
                float tt = __fsub_rn(g_kp_var[b * CAP + i], mn);
                float vn = __fmul_rn(tt, r);
                float score_var = __fsub_rn(1.0f, vn);
                sc = __fmul_rn(g_kp_rel[b * CAP + i], score_var);
            }
            key = ((unsigned long long)(~f2s(sc)) << 32) | (unsigned)pixel;
        }
        v[rr] = key;
    }

    // comparator: element at lower index gets min if asc
    auto cx = [](unsigned long long& a, unsigned long long& c, bool asc) {
        bool sw = asc ? (a > c) : (a < c);
        if (sw) { unsigned long long tmp = a; a = c; c = tmp; }
    };

    for (int k = 2; k <= CAP; k <<= 1) {
        for (int j = k >> 1; j > 0; j >>= 1) {
            if (j >= 128) {
                // smem exchange stage (partner thread may be in another warp)
#pragma unroll
                for (int rr = 0; rr < 4; rr++) sk[4 * t + rr] = v[rr];
                __syncthreads();
#pragma unroll
                for (int rr = 0; rr < 4; rr++) {
                    int i = 4 * t + rr;
                    unsigned long long p = sk[i ^ j];
                    bool asc = ((i & k) == 0);
                    bool lower = ((i & j) == 0);
                    bool takeMin = (lower == asc);
                    v[rr] = takeMin ? (v[rr] < p ? v[rr] : p) : (v[rr] > p ? v[rr] : p);
                }
                __syncthreads();
            } else if (j >= 4) {
                // warp shuffle stage: partner lane = lane ^ (j/4), j/4 in {1..16}
                int lm = j >> 2;
#pragma unroll
                for (int rr = 0; rr < 4; rr++) {
                    int i = 4 * t + rr;
                    unsigned long long p = __shfl_xor_sync(0xFFFFFFFFu, v[rr], lm);
                    bool asc = ((i & k) == 0);
                    bool lower = ((i & j) == 0);
                    bool takeMin = (lower == asc);
                    v[rr] = takeMin ? (v[rr] < p ? v[rr] : p) : (v[rr] > p ? v[rr] : p);
                }
            } else if (j == 2) {
                // in-register: pairs (0,2) and (1,3); asc from lower element's i
                bool asc0 = (((4 * t + 0) & k) == 0);
                bool asc1 = (((4 * t + 1) & k) == 0);
                cx(v[0], v[2], asc0);
                cx(v[1], v[3], asc1);
            } else {
                // j == 1: pairs (0,1) and (2,3)
                bool asc0 = (((4 * t + 0) & k) == 0);
                bool asc2 = (((4 * t + 2) & k) == 0);
                cx(v[0], v[1], asc0);
                cx(v[2], v[3], asc2);
            }
        }
    }
#pragma unroll
    for (int rr = 0; rr < 4; rr++) g_keys[b * CAP + 4 * t + rr] = v[rr];
}

// fused: emit mk/sc + bicubic sample + final L2 normalize; one warp per point
__global__ void k_feats(float* __restrict__ out_mk, float* __restrict__ out_sc,
                        float* __restrict__ out_ft) {
    int w    = (blockIdx.x * blockDim.x + threadIdx.x) >> 5;
    int lane = threadIdx.x & 31;
    int b = w >> 12;                       // TOPK = 4096 points per batch
    unsigned long long key = g_keys[w];    // CAP == TOPK: dense
    int pixel; float sc;
    if (key == ~0ull) { pixel = 0; sc = -1.0f; }
    else {
        pixel = (int)(unsigned)(key & 0xFFFFFFFFull);
        sc = s2f(~(unsigned)(key >> 32));
    }
    int x = pixel & 255, y = pixel >> 8;
    if (lane == 0) {
        out_mk[w * 2 + 0] = (float)(4 * x);
        out_mk[w * 2 + 1] = (float)(4 * y);
        out_sc[w] = sc;
    }
    float ixf = unnorm((float)(4 * x));
    float iyf = unnorm((float)(4 * y));
    float fx = floorf(ixf), fy = floorf(iyf);
    int x0 = (int)fx, y0 = (int)fy;
    float tx = ixf - fx, ty = iyf - fy;
    float wx[4], wy[4];
    cubicw(tx, wx);
    cubicw(ty, wy);
    float a0 = 0.f, a1 = 0.f;
#pragma unroll
    for (int j = 0; j < 4; j++) {
        int yy = y0 - 1 + j;
        if ((unsigned)yy >= MH) continue;
#pragma unroll
        for (int i = 0; i < 4; i++) {
            int xx = x0 - 1 + i;
            if ((unsigned)xx >= MW) continue;
            float wgt = wy[j] * wx[i];
            const float2* p = (const float2*)(g_desc_t) + ((b << 16) + (yy << 8) + xx) * 32 + lane;
            float2 v = __ldg(p);
            a0 += wgt * v.x;
            a1 += wgt * v.y;
        }
    }
    float ss = a0 * a0 + a1 * a1;
#pragma unroll
    for (int off = 16; off > 0; off >>= 1) ss += __shfl_xor_sync(0xFFFFFFFFu, ss, off);
    float inv = 1.0f / fmaxf(sqrtf(ss), 1e-12f);
    float2 o; o.x = a0 * inv; o.y = a1 * inv;
    ((float2*)out_ft)[w * 32 + lane] = o;
}

// -------- launch --------
extern "C" void kernel_launch(void* const* d_in, const int* in_sizes, int n_in,
                              void* d_out, int out_size) {
    const float* rel  = (const float*)d_in[0];
    const float* var  = (const float*)d_in[1];
    const float* desc = (const float*)d_in[2];
    float* out    = (float*)d_out;
    float* out_mk = out;                        // [8,4096,2]
    float* out_sc = out + NB * TOPK * 2;        // [8,4096]
    float* out_ft = out + NB * TOPK * 3;        // [8,4096,64]

    k_init<<<1, 32>>>();
    k_transpose<<<NB * (NPIX / 64), 256>>>(desc);
    k_nms<<<(NB * NPIX) / 256, 256>>>(rel, var);
    k_sort<<<NB, 1024>>>();
    k_feats<<<(NB * TOPK) / 8, 256>>>(out_mk, out_sc, out_ft);
}

// round 17
// speedup vs baseline: 1.5022x; 1.0739x over previous
#include <cuda_runtime.h>

#define NB   8
#define NC   64
#define MH   256
#define MW   256
#define NPIX (MH*MW)
#define CAP  4096
#define TOPK 4096

// -------- device scratch (no allocations allowed) --------
__device__ float g_desc_t[NB * NPIX * NC];        // normalized desc, NHWC
__device__ int   g_count[NB];
__device__ int   g_minbits;
__device__ int   g_maxbits;
__device__ int   g_kp_pix[NB * CAP];
__device__ float g_kp_var[NB * CAP];
__device__ float g_kp_rel[NB * CAP];
__device__ unsigned long long g_keys[NB * CAP];

// -------- helpers --------
__device__ __forceinline__ unsigned f2s(float f) {
    unsigned u = __float_as_uint(f);
    return (u & 0x80000000u) ? ~u : (u ^ 0x80000000u);
}
__device__ __forceinline__ float s2f(unsigned s) {
    unsigned u = (s & 0x80000000u) ? (s ^ 0x80000000u) : ~s;
    return __uint_as_float(u);
}
__device__ __forceinline__ void cubicw(float t, float* w) {
    const float A = -0.75f;
    float t1 = t + 1.0f;
    w[0] = ((A * t1 - 5.0f * A) * t1 + 8.0f * A) * t1 - 4.0f * A;
    w[1] = ((A + 2.0f) * t - (A + 3.0f)) * t * t + 1.0f;
    float u = 1.0f - t;
    w[2] = ((A + 2.0f) * u - (A + 3.0f)) * u * u + 1.0f;
    float t2 = 2.0f - t;
    w[3] = ((A * t2 - 5.0f * A) * t2 + 8.0f * A) * t2 - 4.0f * A;
}
// Unnorm: HLO reciprocal rewrite (p/1023 -> p*fl(1/1023)), *256 folded (exact), -0.5.
__device__ __forceinline__ float unnorm(float p) {
    const float C = 256.0f / 1023.0f;   // = 256 * fl(1/1023) exactly
    return __fsub_rn(__fmul_rn(p, C), 0.5f);
}

// -------- kernels --------
__global__ void k_init() {
    int t = threadIdx.x;
    if (t < NB) g_count[t] = 0;
    if (t == 0) { g_minbits = 0x7F800000; g_maxbits = 0; }
}

// desc [B,C,H,W] -> g_desc_t [B,H*W,C], fused per-pixel L2 inv-norm.
// 64px x 64ch tiles, float4 global loads AND stores.
__global__ void k_transpose(const float* __restrict__ desc) {
    __shared__ float sh[NC][65];
    __shared__ float sinv[64];
    int b    = blockIdx.x >> 10;           // 1024 tiles per batch
    int base = (blockIdx.x & 1023) * 64;   // 64 pixels per tile
    int tid  = threadIdx.x;                // 256 threads

#pragma unroll
    for (int k = 0; k < 4; k++) {
        int fidx = tid + k * 256;
        int c = fidx >> 4, q = fidx & 15;
        float4 v = *(const float4*)(desc + ((b * NC + c) << 16) + base + q * 4);
        sh[c][q * 4 + 0] = v.x; sh[c][q * 4 + 1] = v.y;
        sh[c][q * 4 + 2] = v.z; sh[c][q * 4 + 3] = v.w;
    }
    __syncthreads();
    {
        int px = tid >> 2, part = tid & 3;
        float ss = 0.f;
#pragma unroll
        for (int i = 0; i < 16; i++) { float v = sh[part * 16 + i][px]; ss += v * v; }
        ss += __shfl_xor_sync(0xFFFFFFFFu, ss, 1);
        ss += __shfl_xor_sync(0xFFFFFFFFu, ss, 2);
        if (part == 0) sinv[px] = 1.0f / fmaxf(sqrtf(ss), 1e-12f);
    }
    __syncthreads();
#pragma unroll
    for (int k = 0; k < 4; k++) {
        int fidx = tid + k * 256;
        int px = fidx >> 4, q = fidx & 15;
        float s = sinv[px];
        float4 v;
        v.x = sh[q * 4 + 0][px] * s; v.y = sh[q * 4 + 1][px] * s;
        v.z = sh[q * 4 + 2][px] * s; v.w = sh[q * 4 + 3][px] * s;
        *(float4*)(g_desc_t + (((b << 16) + base + px) << 6) + q * 4) = v;
    }
}

// NMS + bilinear variance sample + global min/max + compaction
__global__ void k_nms(const float* __restrict__ rel, const float* __restrict__ var) {
    int t = blockIdx.x * blockDim.x + threadIdx.x;
    int b = t >> 16, pix = t & (NPIX - 1);
    int y = pix >> 8, x = pix & 255;
    const float* rb = rel + b * NPIX;
    float v = __ldg(rb + pix);
    int ylo = y - 2 < 0 ? 0 : y - 2, yhi = y + 2 > MH - 1 ? MH - 1 : y + 2;
    int xlo = x - 2 < 0 ? 0 : x - 2, xhi = x + 2 > MW - 1 ? MW - 1 : x + 2;
    float lm = -3.0e38f;
    for (int yy = ylo; yy <= yhi; yy++) {
        const float* rr = rb + (yy << 8);
        for (int xx = xlo; xx <= xhi; xx++) lm = fmaxf(lm, __ldg(rr + xx));
    }
    bool kp = (v == lm) && (v > 0.05f);
    if (kp || pix == 0) {   // pix==0 also covers padding rows' var_s contribution
        const float* vb = var + b * NPIX;
        float ixf = unnorm((float)(4 * x));
        float iyf = unnorm((float)(4 * y));
        float fx = floorf(ixf), fy = floorf(iyf);
        int x0 = (int)fx, y0 = (int)fy;
        float tx = __fsub_rn(ixf, fx), ty = __fsub_rn(iyf, fy);
        float omtx = __fsub_rn(1.0f, tx), omty = __fsub_rn(1.0f, ty);
        auto ld = [&](int yy, int xx) -> float {
            return ((unsigned)yy < MH && (unsigned)xx < MW) ? __ldg(vb + (yy << 8) + xx) : 0.f;
        };
        float v00 = ld(y0, x0),     v01 = ld(y0, x0 + 1);
        float v10 = ld(y0 + 1, x0), v11 = ld(y0 + 1, x0 + 1);
        // fully unfused bilinear (matches reference bit-exactly)
        float top = __fadd_rn(__fmul_rn(v00, omtx), __fmul_rn(v01, tx));
        float bot = __fadd_rn(__fmul_rn(v10, omtx), __fmul_rn(v11, tx));
        float vs  = __fadd_rn(__fmul_rn(top, omty), __fmul_rn(bot, ty));
        atomicMin(&g_minbits, __float_as_int(vs));   // vs >= 0 -> int bits monotone
        atomicMax(&g_maxbits, __float_as_int(vs));
        if (kp) {
            int idx = atomicAdd(&g_count[b], 1);
            if (idx < CAP) {
                g_kp_pix[b * CAP + idx] = pix;
                g_kp_var[b * CAP + idx] = vs;
                g_kp_rel[b * CAP + idx] = v;
            }
        }
    }
}

// shared comparator helpers for the bitonic stages
__device__ __forceinline__ unsigned long long bsel(unsigned long long a,
                                                   unsigned long long p,
                                                   bool takeMin) {
    return takeMin ? (a < p ? a : p) : (a > p ? a : p);
}

// Phase A: keys + per-chunk bitonic sort (stages k=2..1024).
// 32 blocks: batch = blockIdx/4, chunk m = blockIdx%4 (1024 elements).
// Thread t owns global i = m*1024 + 4t + r. asc bits use GLOBAL index, so this
// is exactly the standard network's prefix.
__global__ void k_sort_local() {
    __shared__ unsigned long long sk[1024];
    int b = blockIdx.x >> 2;
    int m = blockIdx.x & 3;
    int t = threadIdx.x;                   // 256 threads
    int gbase = (m << 10) + 4 * t;
    int cnt = g_count[b]; if (cnt > CAP) cnt = CAP;
    float mn = __int_as_float(g_minbits);
    float mx = __int_as_float(g_maxbits);
    float denom = __fadd_rn(__fsub_rn(mx, mn), 1e-6f);
    // HLO scalar-division hoist: divide(X, broadcast(s)) -> X * broadcast(1/s)
    float r = __fdiv_rn(1.0f, denom);

    unsigned long long v[4];
#pragma unroll
    for (int rr = 0; rr < 4; rr++) {
        int i = gbase + rr;
        unsigned long long key = ~0ull;
        if (i < cnt) {
            int pixel = g_kp_pix[b * CAP + i];
            float sc;
            if (pixel == 0) {
                sc = -1.0f;
            } else {
                float tt = __fsub_rn(g_kp_var[b * CAP + i], mn);
                float vn = __fmul_rn(tt, r);
                float score_var = __fsub_rn(1.0f, vn);
                sc = __fmul_rn(g_kp_rel[b * CAP + i], score_var);
            }
            key = ((unsigned long long)(~f2s(sc)) << 32) | (unsigned)pixel;
        }
        v[rr] = key;
    }

    auto cx = [](unsigned long long& a, unsigned long long& c, bool asc) {
        bool sw = asc ? (a > c) : (a < c);
        if (sw) { unsigned long long tmp = a; a = c; c = tmp; }
    };

    for (int k = 2; k <= 1024; k <<= 1) {
        for (int j = k >> 1; j > 0; j >>= 1) {
            if (j >= 128) {
                // smem exchange (local indices within the 1024-chunk)
#pragma unroll
                for (int rr = 0; rr < 4; rr++) sk[4 * t + rr] = v[rr];
                __syncthreads();
#pragma unroll
                for (int rr = 0; rr < 4; rr++) {
                    int li = 4 * t + rr;
                    unsigned long long p = sk[li ^ j];
                    int i = (m << 10) + li;
                    bool asc = ((i & k) == 0);
                    bool takeMin = (((i & j) == 0) == asc);
                    v[rr] = bsel(v[rr], p, takeMin);
                }
                __syncthreads();
            } else if (j >= 4) {
                int lmask = j >> 2;        // 1..16, intra-warp
#pragma unroll
                for (int rr = 0; rr < 4; rr++) {
                    int i = gbase + rr;
                    unsigned long long p = __shfl_xor_sync(0xFFFFFFFFu, v[rr], lmask);
                    bool asc = ((i & k) == 0);
                    bool takeMin = (((i & j) == 0) == asc);
                    v[rr] = bsel(v[rr], p, takeMin);
                }
            } else if (j == 2) {
                bool asc0 = (((gbase + 0) & k) == 0);
                bool asc1 = (((gbase + 1) & k) == 0);
                cx(v[0], v[2], asc0);
                cx(v[1], v[3], asc1);
            } else {
                bool asc0 = (((gbase + 0) & k) == 0);
                bool asc2 = (((gbase + 2) & k) == 0);
                cx(v[0], v[1], asc0);
                cx(v[2], v[3], asc2);
            }
        }
    }
#pragma unroll
    for (int rr = 0; rr < 4; rr++) g_keys[b * CAP + gbase + rr] = v[rr];
}

// Phase B: final merge stages k=2048, 4096 (23 steps). One block per batch.
__global__ void k_sort_merge() {
    __shared__ unsigned long long sk[CAP];
    int b = blockIdx.x;
    int t = threadIdx.x;                   // 1024 threads

    unsigned long long v[4];
#pragma unroll
    for (int rr = 0; rr < 4; rr++) v[rr] = g_keys[b * CAP + 4 * t + rr];

    auto cx = [](unsigned long long& a, unsigned long long& c, bool asc) {
        bool sw = asc ? (a > c) : (a < c);
        if (sw) { unsigned long long tmp = a; a = c; c = tmp; }
    };

    for (int k = 2048; k <= CAP; k <<= 1) {
        for (int j = k >> 1; j > 0; j >>= 1) {
            if (j >= 128) {
#pragma unroll
                for (int rr = 0; rr < 4; rr++) sk[4 * t + rr] = v[rr];
                __syncthreads();
#pragma unroll
                for (int rr = 0; rr < 4; rr++) {
                    int i = 4 * t + rr;
                    unsigned long long p = sk[i ^ j];
                    bool asc = ((i & k) == 0);
                    bool takeMin = (((i & j) == 0) == asc);
                    v[rr] = bsel(v[rr], p, takeMin);
                }
                __syncthreads();
            } else if (j >= 4) {
                int lmask = j >> 2;
#pragma unroll
                for (int rr = 0; rr < 4; rr++) {
                    int i = 4 * t + rr;
                    unsigned long long p = __shfl_xor_sync(0xFFFFFFFFu, v[rr], lmask);
                    bool asc = ((i & k) == 0);
                    bool takeMin = (((i & j) == 0) == asc);
                    v[rr] = bsel(v[rr], p, takeMin);
                }
            } else if (j == 2) {
                bool asc0 = (((4 * t + 0) & k) == 0);
                bool asc1 = (((4 * t + 1) & k) == 0);
                cx(v[0], v[2], asc0);
                cx(v[1], v[3], asc1);
            } else {
                bool asc0 = (((4 * t + 0) & k) == 0);
                bool asc2 = (((4 * t + 2) & k) == 0);
                cx(v[0], v[1], asc0);
                cx(v[2], v[3], asc2);
            }
        }
    }
#pragma unroll
    for (int rr = 0; rr < 4; rr++) g_keys[b * CAP + 4 * t + rr] = v[rr];
}

// fused: emit mk/sc + bicubic sample + final L2 normalize; one warp per point
__global__ void k_feats(float* __restrict__ out_mk, float* __restrict__ out_sc,
                        float* __restrict__ out_ft) {
    int w    = (blockIdx.x * blockDim.x + threadIdx.x) >> 5;
    int lane = threadIdx.x & 31;
    int b = w >> 12;                       // TOPK = 4096 points per batch
    unsigned long long key = g_keys[w];    // CAP == TOPK: dense
    int pixel; float sc;
    if (key == ~0ull) { pixel = 0; sc = -1.0f; }
    else {
        pixel = (int)(unsigned)(key & 0xFFFFFFFFull);
        sc = s2f(~(unsigned)(key >> 32));
    }
    int x = pixel & 255, y = pixel >> 8;
    if (lane == 0) {
        out_mk[w * 2 + 0] = (float)(4 * x);
        out_mk[w * 2 + 1] = (float)(4 * y);
        out_sc[w] = sc;
    }
    float ixf = unnorm((float)(4 * x));
    float iyf = unnorm((float)(4 * y));
    float fx = floorf(ixf), fy = floorf(iyf);
    int x0 = (int)fx, y0 = (int)fy;
    float tx = ixf - fx, ty = iyf - fy;
    float wx[4], wy[4];
    cubicw(tx, wx);
    cubicw(ty, wy);
    float a0 = 0.f, a1 = 0.f;
#pragma unroll
    for (int j = 0; j < 4; j++) {
        int yy = y0 - 1 + j;
        if ((unsigned)yy >= MH) continue;
#pragma unroll
        for (int i = 0; i < 4; i++) {
            int xx = x0 - 1 + i;
            if ((unsigned)xx >= MW) continue;
            float wgt = wy[j] * wx[i];
            const float2* p = (const float2*)(g_desc_t) + ((b << 16) + (yy << 8) + xx) * 32 + lane;
            float2 v = __ldg(p);
            a0 += wgt * v.x;
            a1 += wgt * v.y;
        }
    }
    float ss = a0 * a0 + a1 * a1;
#pragma unroll
    for (int off = 16; off > 0; off >>= 1) ss += __shfl_xor_sync(0xFFFFFFFFu, ss, off);
    float inv = 1.0f / fmaxf(sqrtf(ss), 1e-12f);
    float2 o; o.x = a0 * inv; o.y = a1 * inv;
    ((float2*)out_ft)[w * 32 + lane] = o;
}

// -------- launch --------
extern "C" void kernel_launch(void* const* d_in, const int* in_sizes, int n_in,
                              void* d_out, int out_size) {
    const float* rel  = (const float*)d_in[0];
    const float* var  = (const float*)d_in[1];
    const float* desc = (const float*)d_in[2];
    float* out    = (float*)d_out;
    float* out_mk = out;                        // [8,4096,2]
    float* out_sc = out + NB * TOPK * 2;        // [8,4096]
    float* out_ft = out + NB * TOPK * 3;        // [8,4096,64]

    k_init<<<1, 32>>>();
    k_transpose<<<NB * (NPIX / 64), 256>>>(desc);
    k_nms<<<(NB * NPIX) / 256, 256>>>(rel, var);
    k_sort_local<<<NB * 4, 256>>>();
    k_sort_merge<<<NB, 1024>>>();
    k_feats<<<(NB * TOPK) / 8, 256>>>(out_mk, out_sc, out_ft);
}